// round 15
// baseline (speedup 1.0000x reference)
#include <cuda_runtime.h>
#include <cuda_bf16.h>
#include <mma.h>
using namespace nvcuda;
typedef __nv_bfloat16 bf;

#define NN 50000
#define EE 800000
#define NFD 64
#define EFD 32
#define HH 96
#define OUTD 64
#define LL 4
#define GG 64
#define NH (NN*HH)
#define STAGE_B 33792         // Ah[5120]+Al[5120]+Wh[3328]+Wl[3328] bf16 bytes
#define SMEM_DYN (2*STAGE_B)  // 67584

// ------------------------------ scratch ------------------------------------
// PT, PS, AGG(0-init) | fPT,fPS,fU,bcomb (LL*HH each) | invdeg
__device__ float d_f[3*NH + 4*LL*HH + NN];
// bf planes: tpa h/l, tpb h/l, gmp h/l, ghp h/l, gh2 h/l, ea h/l
__device__ bf d_pb[4*NH + 6*GG*HH + 2*(size_t)EE*EFD];
// weight planes (each array: h plane then l plane)
__device__ bf d_wpb[380928];
__device__ int4 d_edat[EE];
// deg[NN], gcnt[GG+1] | rowptr[NN+1], cursor[NN], gstart[GG+1]
__device__ int d_i[NN + (GG+1) + (NN+1) + NN + (GG+1)];

__device__ __forceinline__ void split1(float x, bf& h, bf& l) {
    h = __float2bfloat16_rn(x);
    l = __float2bfloat16_rn(x - __bfloat162float(h));
}
__device__ __forceinline__ void cpa16(bf* dst, const bf* src) {
    unsigned s = (unsigned)__cvta_generic_to_shared(dst);
    asm volatile("cp.async.cg.shared.global [%0], [%1], 16;" :: "r"(s), "l"(src));
}

// ------------------------------ setup --------------------------------------
__global__ void hist_both(const int* __restrict__ tgt, const int* __restrict__ batch,
                          int* __restrict__ deg, int* __restrict__ gcnt) {
    int i = blockIdx.x*blockDim.x + threadIdx.x;
    if (i < EE) atomicAdd(&deg[tgt[i]], 1);
    else if (i < EE + NN) atomicAdd(&gcnt[batch[i - EE]], 1);
}

__device__ void scan_seg(const int* __restrict__ in, int* __restrict__ out,
                         int* __restrict__ copy, int n, int* sums) {
    int lane = threadIdx.x & 31, wid = threadIdx.x >> 5, nwarp = blockDim.x >> 5;
    int offset = 0;
    for (int base = 0; base < n; base += blockDim.x) {
        int i = base + threadIdx.x;
        int v = (i < n) ? in[i] : 0, x = v;
        #pragma unroll
        for (int d = 1; d < 32; d <<= 1) { int y = __shfl_up_sync(~0u, x, d); if (lane >= d) x += y; }
        if (lane == 31) sums[wid] = x;
        __syncthreads();
        if (wid == 0) {
            int s = (lane < nwarp) ? sums[lane] : 0;
            #pragma unroll
            for (int d = 1; d < 32; d <<= 1) { int y = __shfl_up_sync(~0u, s, d); if (lane >= d) s += y; }
            sums[lane] = s;
        }
        __syncthreads();
        int warp_off = (wid > 0) ? sums[wid-1] : 0;
        if (i < n) { int val = offset + warp_off + x - v; out[i] = val; if (copy) copy[i] = val; }
        int total = sums[nwarp-1];
        __syncthreads();
        offset += total;
    }
    if (threadIdx.x == 0) out[n] = offset;
    __syncthreads();
}
__global__ void scan_both(const int* __restrict__ deg, int* __restrict__ rowptr,
                          int* __restrict__ cursor, const int* __restrict__ gcnt,
                          int* __restrict__ gstart) {
    __shared__ int sums[32];
    scan_seg(deg, rowptr, cursor, NN, sums);
    scan_seg(gcnt, gstart, nullptr, GG, sums);
}

__global__ void scatter_kernel(const int* __restrict__ src, const int* __restrict__ tgt,
                               int* __restrict__ cursor, int4* __restrict__ edat) {
    int e = blockIdx.x*blockDim.x + threadIdx.x;
    if (e < EE) {
        int t = tgt[e];
        int p = atomicAdd(&cursor[t], 1);
        edat[p] = make_int4(src[e], t, e, 0);
    }
}

// gather+split edge_attr (x4) into planes + invdeg
#define E4 (EE*EFD/4)
__global__ void gather_split(const float* __restrict__ EA, const int4* __restrict__ edat,
                             const int* __restrict__ deg,
                             bf* __restrict__ eah, bf* __restrict__ eal,
                             float* __restrict__ invdeg) {
    int idx = blockIdx.x*blockDim.x + threadIdx.x;
    if (idx < E4) {
        int i = idx >> 3, f4 = idx & 7;
        int e = edat[i].z;
        float4 v = ((const float4*)(EA + (size_t)e*EFD))[f4];
        bf h0,l0,h1,l1,h2,l2,h3,l3;
        split1(v.x,h0,l0); split1(v.y,h1,l1); split1(v.z,h2,l2); split1(v.w,h3,l3);
        unsigned uh0 = ((unsigned)__bfloat16_as_ushort(h1)<<16)|__bfloat16_as_ushort(h0);
        unsigned uh1 = ((unsigned)__bfloat16_as_ushort(h3)<<16)|__bfloat16_as_ushort(h2);
        unsigned ul0 = ((unsigned)__bfloat16_as_ushort(l1)<<16)|__bfloat16_as_ushort(l0);
        unsigned ul1 = ((unsigned)__bfloat16_as_ushort(l3)<<16)|__bfloat16_as_ushort(l2);
        *(uint2*)(eah + (size_t)idx*4) = make_uint2(uh0, uh1);
        *(uint2*)(eal + (size_t)idx*4) = make_uint2(ul0, ul1);
    } else if (idx < E4 + NN) {
        int n = idx - E4;
        invdeg[n] = 1.f / (float)max(deg[n], 1);
    }
}

struct PackArgs { const float* src[8]; bf* dsth[8]; bf* dstl[8]; int n[8]; };
__global__ void pack_kernel(PackArgs a) {
    int s = blockIdx.y;
    int i = blockIdx.x*blockDim.x + threadIdx.x;
    if (i < a.n[s]) { bf h, l; split1(a.src[s][i], h, l); a.dsth[s][i] = h; a.dstl[s][i] = l; }
}

// Per-layer weight folds. blockIdx.x = l*4 + which. (see R12 comment)
__global__ void fold_kernel(
    const float* __restrict__ emb_w2, const float* __restrict__ emb_b2,
    const float* __restrict__ msg_w1, const float* __restrict__ msg_b1,
    const float* __restrict__ msg_w2, const float* __restrict__ msg_b2,
    const float* __restrict__ upd_w1, const float* __restrict__ upd_b1,
    const float* __restrict__ upd_w2, const float* __restrict__ upd_b2,
    bf* __restrict__ wfah, bf* __restrict__ wfal,
    bf* __restrict__ wfbh, bf* __restrict__ wfbl,
    bf* __restrict__ wu1h, bf* __restrict__ wu1l,
    float* __restrict__ fPT, float* __restrict__ fPS, float* __restrict__ fU,
    float* __restrict__ bcomb)
{
    int l = blockIdx.x >> 2, which = blockIdx.x & 3;
    const float* P;  const float* pb;
    const float* W;  const float* badd = nullptr;
    bf* Wh; bf* Wl;  float* bout;
    if (which == 3) {
        P = msg_w2 + (size_t)l*HH*HH;  pb = msg_b2 + l*HH;
        W = upd_w1 + (size_t)l*2*HH*HH + HH*HH;
        Wh = wu1h + (size_t)l*2*HH*HH + HH*HH; Wl = wu1l + (size_t)l*2*HH*HH + HH*HH;
        bout = bcomb + l*HH;
    } else {
        P  = (l == 0) ? emb_w2 : upd_w2 + (size_t)(l-1)*HH*HH;
        pb = (l == 0) ? emb_b2 : upd_b2 + (size_t)(l-1)*HH;
        if (which == 0) { W = msg_w1 + (size_t)l*(2*HH+EFD)*HH;
                          Wh = wfah + (size_t)l*HH*HH; Wl = wfal + (size_t)l*HH*HH;
                          bout = fPT + l*HH; badd = msg_b1 + l*HH; }
        else if (which == 1) { W = msg_w1 + (size_t)l*(2*HH+EFD)*HH + HH*HH;
                               Wh = wfbh + (size_t)l*HH*HH; Wl = wfbl + (size_t)l*HH*HH;
                               bout = fPS + l*HH; }
        else { W = upd_w1 + (size_t)l*2*HH*HH;
               Wh = wu1h + (size_t)l*2*HH*HH; Wl = wu1l + (size_t)l*2*HH*HH;
               bout = fU + l*HH; badd = upd_b1 + l*HH; }
    }
    for (int idx = threadIdx.x; idx < HH*HH; idx += blockDim.x) {
        int k = idx / HH, c = idx - k*HH;
        float s = 0.f;
        #pragma unroll 8
        for (int j = 0; j < HH; j++) s += P[k*HH + j] * W[j*HH + c];
        bf h, lo; split1(s, h, lo); Wh[idx] = h; Wl[idx] = lo;
    }
    for (int c = threadIdx.x; c < HH; c += blockDim.x) {
        float s = 0.f;
        for (int j = 0; j < HH; j++) s += pb[j] * W[j*HH + c];
        if (badd) s += badd[c];
        bout[c] = s;
    }
}

// --------------------------- MMA helper ------------------------------------
__device__ __forceinline__ void do_mma32(
    wmma::fragment<wmma::accumulator,16,16,16,float> (&acc)[2][3],
    const bf* Ah, const bf* Al, const bf* Wh, const bf* Wl, int wm, int wn) {
    #pragma unroll
    for (int ks = 0; ks < 32; ks += 16) {
        wmma::fragment<wmma::matrix_a,16,16,16,bf,wmma::row_major> ah[2], al2[2];
        wmma::fragment<wmma::matrix_b,16,16,16,bf,wmma::row_major> bh[3], bl[3];
        #pragma unroll
        for (int i = 0; i < 2; i++) {
            wmma::load_matrix_sync(ah[i],  &Ah[(wm + i*16)*40 + ks], 40);
            wmma::load_matrix_sync(al2[i], &Al[(wm + i*16)*40 + ks], 40);
        }
        #pragma unroll
        for (int j = 0; j < 3; j++) {
            wmma::load_matrix_sync(bh[j], &Wh[ks*104 + wn + j*16], 104);
            wmma::load_matrix_sync(bl[j], &Wl[ks*104 + wn + j*16], 104);
        }
        #pragma unroll
        for (int i = 0; i < 2; i++)
            #pragma unroll
            for (int j = 0; j < 3; j++) {
                wmma::mma_sync(acc[i][j], ah[i],  bh[j], acc[i][j]);
                wmma::mma_sync(acc[i][j], ah[i],  bl[j], acc[i][j]);
                wmma::mma_sync(acc[i][j], al2[i], bh[j], acc[i][j]);
            }
    }
}

// ------------- GEMM: cp.async double-buffered, plane format -----------------
__global__ void __launch_bounds__(256, 2) gemm_tc(
    const bf* __restrict__ A1h, const bf* __restrict__ A1l, int lda1, int K1, int K,
    const float* __restrict__ A2f, const float* __restrict__ Ainv, int lda2,
    const bf* __restrict__ Wah, const bf* __restrict__ Wal,
    const bf* __restrict__ Wbh, const bf* __restrict__ Wbl,
    const float* __restrict__ ba, const float* __restrict__ bb,
    const float* __restrict__ bx, const int* __restrict__ degmask, int relu,
    bf* __restrict__ oPh, bf* __restrict__ oPl,
    float* __restrict__ oF0, float* __restrict__ oF1, float* __restrict__ zbuf,
    int ldO, int Ncols, int M)
{
    extern __shared__ __align__(16) char sm[];
    float* Cs = (float*)sm;  // epilogue reuse (all cp.async retired by then)

    const bf* Wgh = blockIdx.y ? Wbh : Wah;
    const bf* Wgl = blockIdx.y ? Wbl : Wal;
    const float* b = blockIdx.y ? bb : ba;
    float* oF = blockIdx.y ? oF1 : oF0;

    int tid = threadIdx.x, wid = tid >> 5;
    int bm0 = blockIdx.x * 128;
    int wm = (wid & 3) * 32, wn = (wid >> 2) * 48;
    int nch = K / 32;
    int segw = Ncols >> 3, wtot = 32 * segw;

    auto issue = [&](int ci) {
        int k0 = ci * 32;
        bf* Ah = (bf*)(sm + (ci & 1) * STAGE_B);
        bf* Al = Ah + 5120;
        bf* Wh = Al + 5120;
        bf* Wl = Wh + 3328;
        if (k0 < K1) {
            #pragma unroll
            for (int i = 0; i < 2; i++) {
                int p = tid + 256*i;                 // 512 segs
                int r = p >> 2, seg = p & 3;
                size_t go = (size_t)(bm0 + r)*lda1 + k0 + seg*8;
                cpa16(Ah + r*40 + seg*8, A1h + go);
                cpa16(Al + r*40 + seg*8, A1l + go);
            }
        } else {
            #pragma unroll
            for (int i = 0; i < 8; i++) {
                int p = tid + 256*i; int r = p >> 4, kc = (p & 15) << 1;
                int row = bm0 + r;
                float v0 = 0.f, v1 = 0.f;
                if (row < M) {
                    float d = Ainv ? Ainv[row] : 1.f;
                    const float* a = A2f + (size_t)row*lda2 + (k0 - K1) + kc;
                    v0 = a[0]*d; v1 = a[1]*d;
                }
                bf h0,l0,h1,l1; split1(v0,h0,l0); split1(v1,h1,l1);
                Ah[r*40+kc] = h0; Ah[r*40+kc+1] = h1;
                Al[r*40+kc] = l0; Al[r*40+kc+1] = l1;
            }
        }
        #pragma unroll
        for (int i = 0; i < 2; i++) {
            int p = tid + 256*i;
            if (p < wtot) {
                int kk = p / segw, seg = p - kk*segw;
                size_t go = (size_t)(k0 + kk)*Ncols + seg*8;
                cpa16(Wh + kk*104 + seg*8, Wgh + go);
                cpa16(Wl + kk*104 + seg*8, Wgl + go);
            }
        }
        asm volatile("cp.async.commit_group;");
    };

    wmma::fragment<wmma::accumulator,16,16,16,float> acc[2][3];
    #pragma unroll
    for (int i = 0; i < 2; i++)
        #pragma unroll
        for (int j = 0; j < 3; j++) wmma::fill_fragment(acc[i][j], 0.f);

    issue(0);
    for (int c = 0; c < nch; c++) {
        if (c + 1 < nch) {
            issue(c + 1);
            asm volatile("cp.async.wait_group 1;");
        } else {
            asm volatile("cp.async.wait_group 0;");
        }
        __syncthreads();
        bf* Ah = (bf*)(sm + (c & 1) * STAGE_B);
        bf* Al = Ah + 5120;
        bf* Wh = Al + 5120;
        bf* Wl = Wh + 3328;
        do_mma32(acc, Ah, Al, Wh, Wl, wm, wn);
        __syncthreads();
    }

    #pragma unroll
    for (int i = 0; i < 2; i++)
        #pragma unroll
        for (int j = 0; j < 3; j++)
            wmma::store_matrix_sync(&Cs[(wm + i*16)*96 + wn + j*16], acc[i][j], 96,
                                    wmma::mem_row_major);
    __syncthreads();
    for (int p = tid; p < 6144; p += 256) {
        int r = p / 48, cc = (p - r*48) * 2;
        int row = bm0 + r;
        if (row >= M) continue;
        bool xb = bx && degmask[row] > 0;
        #pragma unroll
        for (int q = 0; q < 2; q++) {
            int c = cc + q;
            if (c >= Ncols) break;
            float v = Cs[r*96 + c];
            if (b) v += b[c];
            if (xb) v += bx[c];
            if (relu) v = fmaxf(v, 0.f);
            size_t o = (size_t)row*ldO + c;
            if (oPh) { bf h, l; split1(v, h, l); oPh[o] = h; oPl[o] = l; }
            if (oF) oF[o] = v;
            if (zbuf && blockIdx.y == 0) zbuf[o] = 0.f;
        }
    }
}

// ------------------------- fused edge kernel --------------------------------
__global__ void __launch_bounds__(256, 2) edge_fused(
    const bf* __restrict__ eah, const bf* __restrict__ eal,
    const bf* __restrict__ ech, const bf* __restrict__ ecl,
    const float* __restrict__ PT, const float* __restrict__ PS,
    const int4* __restrict__ edat, float* __restrict__ AGG)
{
    __shared__ __align__(16) char smraw[49152];
    bf* Ah = (bf*)smraw;
    bf* Al = Ah + 5120;
    bf* Wh = Al + 5120;
    bf* Wl = Wh + 3328;
    float* pes = (float*)smraw;     // [128][96]

    int tid = threadIdx.x, wid = tid >> 5, lane = tid & 31;
    int e0 = blockIdx.x * 128;
    int wm = (wid & 3) * 32, wn = (wid >> 2) * 48;

    #pragma unroll
    for (int i = 0; i < 2; i++) {
        int p = tid + 256*i;                 // 512: r in [0,128), seg in [0,4)
        int r = p >> 2, seg = p & 3;
        size_t go = (size_t)(e0 + r)*EFD + seg*8;
        *(uint4*)&Ah[r*40 + seg*8] = *(const uint4*)(eah + go);
        *(uint4*)&Al[r*40 + seg*8] = *(const uint4*)(eal + go);
    }
    #pragma unroll
    for (int i = 0; i < 2; i++) {
        int p = tid + 256*i;
        if (p < 384) {                       // 32 rows x 12 segs
            int kk = p / 12, seg = p - kk*12;
            size_t go = (size_t)kk*96 + seg*8;
            *(uint4*)&Wh[kk*104 + seg*8] = *(const uint4*)(ech + go);
            *(uint4*)&Wl[kk*104 + seg*8] = *(const uint4*)(ecl + go);
        }
    }
    __syncthreads();

    wmma::fragment<wmma::accumulator,16,16,16,float> acc[2][3];
    #pragma unroll
    for (int i = 0; i < 2; i++)
        #pragma unroll
        for (int j = 0; j < 3; j++) wmma::fill_fragment(acc[i][j], 0.f);
    do_mma32(acc, Ah, Al, Wh, Wl, wm, wn);
    __syncthreads();
    #pragma unroll
    for (int i = 0; i < 2; i++)
        #pragma unroll
        for (int j = 0; j < 3; j++)
            wmma::store_matrix_sync(&pes[(wm + i*16)*96 + wn + j*16], acc[i][j], 96,
                                    wmma::mem_row_major);
    __syncthreads();

    // pipelined aggregation
    int base = wid * 16;
    int4 ed = edat[e0 + base];
    float ps0 = PS[ed.x*96 + lane];
    float ps1 = PS[ed.x*96 + lane + 32];
    float ps2 = PS[ed.x*96 + lane + 64];
    int cur = -1;
    float a0 = 0.f, a1 = 0.f, a2 = 0.f, p0 = 0.f, p1 = 0.f, p2 = 0.f;
    #pragma unroll 4
    for (int j = 0; j < 16; j++) {
        int4 edn; float q0 = 0.f, q1 = 0.f, q2 = 0.f;
        if (j < 15) {
            edn = edat[e0 + base + j + 1];
            q0 = PS[edn.x*96 + lane];
            q1 = PS[edn.x*96 + lane + 32];
            q2 = PS[edn.x*96 + lane + 64];
        }
        int t = ed.y;
        if (t != cur) {
            if (cur >= 0) {
                atomicAdd(&AGG[cur*96 + lane],      a0);
                atomicAdd(&AGG[cur*96 + lane + 32], a1);
                atomicAdd(&AGG[cur*96 + lane + 64], a2);
            }
            cur = t; a0 = a1 = a2 = 0.f;
            p0 = PT[t*96 + lane]; p1 = PT[t*96 + lane + 32]; p2 = PT[t*96 + lane + 64];
        }
        const float* pr = &pes[(base + j)*96];
        a0 += fmaxf(p0 + ps0 + pr[lane],      0.f);
        a1 += fmaxf(p1 + ps1 + pr[lane + 32], 0.f);
        a2 += fmaxf(p2 + ps2 + pr[lane + 64], 0.f);
        ed = edn; ps0 = q0; ps1 = q1; ps2 = q2;
    }
    if (cur >= 0) {
        atomicAdd(&AGG[cur*96 + lane],      a0);
        atomicAdd(&AGG[cur*96 + lane + 32], a1);
        atomicAdd(&AGG[cur*96 + lane + 64], a2);
    }
}

__global__ void pool_kernel(const bf* __restrict__ hph, const bf* __restrict__ hpl,
                            const int* __restrict__ gstart,
                            bf* __restrict__ gmh, bf* __restrict__ gml) {
    int g = blockIdx.x, f = threadIdx.x;
    int beg = gstart[g], end = gstart[g+1];
    float s = 0.f;
    for (int r = beg; r < end; r++)
        s += __bfloat162float(hph[(size_t)r*96 + f]) + __bfloat162float(hpl[(size_t)r*96 + f]);
    s /= (float)max(end - beg, 1);
    bf h, l; split1(s, h, l);
    gmh[g*96 + f] = h; gml[g*96 + f] = l;
}

// ------------------------------- host --------------------------------------
extern "C" void kernel_launch(void* const* d_in, const int* in_sizes, int n_in,
                              void* d_out, int out_size) {
    const float* x          = (const float*)d_in[0];
    const float* edge_attr  = (const float*)d_in[1];
    const int*   edge_index = (const int*)d_in[2];
    const int*   batch      = (const int*)d_in[3];
    const float* emb_w1 = (const float*)d_in[4];  const float* emb_b1 = (const float*)d_in[5];
    const float* emb_w2 = (const float*)d_in[6];  const float* emb_b2 = (const float*)d_in[7];
    const float* msg_w1 = (const float*)d_in[8];  const float* msg_b1 = (const float*)d_in[9];
    const float* msg_w2 = (const float*)d_in[10]; const float* msg_b2 = (const float*)d_in[11];
    const float* upd_w1 = (const float*)d_in[12]; const float* upd_b1 = (const float*)d_in[13];
    const float* upd_w2 = (const float*)d_in[14]; const float* upd_b2 = (const float*)d_in[15];
    const float* head_w1 = (const float*)d_in[16]; const float* head_b1 = (const float*)d_in[17];
    const float* head_w2 = (const float*)d_in[18]; const float* head_b2 = (const float*)d_in[19];

    cudaFuncSetAttribute(gemm_tc, cudaFuncAttributeMaxDynamicSharedMemorySize, SMEM_DYN);

    float* f = nullptr; bf* pb = nullptr; bf* wb = nullptr;
    int* ib = nullptr; int4* edat = nullptr;
    cudaGetSymbolAddress((void**)&f, d_f);
    cudaGetSymbolAddress((void**)&pb, d_pb);
    cudaGetSymbolAddress((void**)&wb, d_wpb);
    cudaGetSymbolAddress((void**)&ib, d_i);
    cudaGetSymbolAddress((void**)&edat, d_edat);

    float* PT = f;  float* PS = f + NH;  float* AGG = f + 2*NH;
    float* fPT = f + 3*NH;          float* fPS = fPT + LL*HH;
    float* fU  = fPS + LL*HH;       float* bcomb = fU + LL*HH;
    float* invdeg = bcomb + LL*HH;

    bf* tpah = pb;            bf* tpal = tpah + NH;
    bf* tpbh = tpal + NH;     bf* tpbl = tpbh + NH;
    bf* gmh  = tpbl + NH;     bf* gml  = gmh + GG*HH;
    bf* ghh  = gml + GG*HH;   bf* ghl  = ghh + GG*HH;
    bf* g2h  = ghl + GG*HH;   bf* g2l  = g2h + GG*HH;
    bf* eah  = g2l + GG*HH;   bf* eal  = eah + (size_t)EE*EFD;

    bf* ewp1h = wb;             bf* ewp1l = ewp1h + 6144;
    bf* wfah = ewp1l + 6144;    bf* wfal = wfah + 36864;
    bf* wfbh = wfal + 36864;    bf* wfbl = wfbh + 36864;
    bf* wu1h = wfbl + 36864;    bf* wu1l = wu1h + 73728;
    bf* u23h = wu1l + 73728;    bf* u23l = u23h + 9216;
    bf* hw1h = u23l + 9216;     bf* hw1l = hw1h + 9216;
    bf* hw2h = hw1l + 9216;     bf* hw2l = hw2h + 6144;
    bf* ech  = hw2l + 6144;     bf* ecl  = ech + 12288;

    int* deg = ib;                 int* gcnt = deg + NN;
    int* rowptr = gcnt + GG + 1;   int* cursor = rowptr + NN + 1;
    int* gstart = cursor + NN;

    const int* src = edge_index;
    const int* tgt = edge_index + EE;

    int nb = (NN + 127)/128;

    // ---- weight chain first; dual PT/PS GEMM at ncu slot 4 ----
    {
        PackArgs a;
        a.src[0]=emb_w1;  a.dsth[0]=ewp1h; a.dstl[0]=ewp1l; a.n[0]=NFD*HH;
        for (int l = 0; l < LL; l++) {
            a.src[1+l] = msg_w1 + (size_t)l*(2*HH+EFD)*HH + 2*HH*HH;  // W1c
            a.dsth[1+l] = ech + (size_t)l*EFD*HH;
            a.dstl[1+l] = ecl + (size_t)l*EFD*HH;
            a.n[1+l] = EFD*HH;
        }
        a.src[5]=upd_w2 + (size_t)3*HH*HH; a.dsth[5]=u23h; a.dstl[5]=u23l; a.n[5]=HH*HH;
        a.src[6]=head_w1; a.dsth[6]=hw1h; a.dstl[6]=hw1l; a.n[6]=HH*HH;
        a.src[7]=head_w2; a.dsth[7]=hw2h; a.dstl[7]=hw2l; a.n[7]=HH*OUTD;
        dim3 g((HH*HH + 255)/256, 8);
        pack_kernel<<<g, 256>>>(a);                                   // 1
    }
    fold_kernel<<<4*LL, 256>>>(emb_w2, emb_b2, msg_w1, msg_b1, msg_w2, msg_b2,
                               upd_w1, upd_b1, upd_w2, upd_b2,
                               wfah, wfal, wfbh, wfbl, wu1h, wu1l,
                               fPT, fPS, fU, bcomb);                  // 2
    // embed stage-1: tpa = relu(x@ew1 + eb1)  (x fp32 path, K1=0)
    gemm_tc<<<nb, 256, SMEM_DYN>>>(nullptr, nullptr, 0, 0, NFD, x, nullptr, NFD,
                                   ewp1h, ewp1l, nullptr, nullptr,
                                   emb_b1, nullptr, nullptr, nullptr, 1,
                                   tpah, tpal, nullptr, nullptr, nullptr, HH, HH, NN); // 3
    // layer-0 PT/PS (dual; y==0 zeroes AGG)                          // 4 <- ncu
    gemm_tc<<<dim3(nb,2), 256, SMEM_DYN>>>(tpah, tpal, HH, HH, HH, nullptr, nullptr, 0,
                                           wfah, wfal, wfbh, wfbl,
                                           fPT, fPS, nullptr, nullptr, 0,
                                           nullptr, nullptr, PT, PS, AGG, HH, HH, NN);

    // ---- graph setup ----
    cudaMemsetAsync(deg, 0, (NN + GG + 1)*sizeof(int));
    hist_both<<<(EE + NN + 255)/256, 256>>>(tgt, batch, deg, gcnt);
    scan_both<<<1, 1024>>>(deg, rowptr, cursor, gcnt, gstart);
    scatter_kernel<<<(EE + 255)/256, 256>>>(src, tgt, cursor, edat);
    gather_split<<<(E4 + NN + 255)/256, 256>>>(edge_attr, edat, deg, eah, eal, invdeg);

    bf* tch = tpah; bf* tcl = tpal;
    bf* tnh = tpbh; bf* tnl = tpbl;
    for (int l = 0; l < LL; l++) {
        if (l > 0) {
            gemm_tc<<<dim3(nb,2), 256, SMEM_DYN>>>(tch, tcl, HH, HH, HH, nullptr, nullptr, 0,
                wfah + (size_t)l*HH*HH, wfal + (size_t)l*HH*HH,
                wfbh + (size_t)l*HH*HH, wfbl + (size_t)l*HH*HH,
                fPT + l*HH, fPS + l*HH, nullptr, nullptr, 0,
                nullptr, nullptr, PT, PS, AGG, HH, HH, NN);
        }
        edge_fused<<<EE/128, 256>>>(eah, eal, ech + (size_t)l*EFD*HH, ecl + (size_t)l*EFD*HH,
                                    PT, PS, edat, AGG);
        gemm_tc<<<nb, 256, SMEM_DYN>>>(tch, tcl, HH, HH, 2*HH, AGG, invdeg, HH,
            wu1h + (size_t)l*2*HH*HH, wu1l + (size_t)l*2*HH*HH, nullptr, nullptr,
            fU + l*HH, nullptr, bcomb + l*HH, deg, 1,
            tnh, tnl, nullptr, nullptr, nullptr, HH, HH, NN);
        bf* t;
        t = tch; tch = tnh; tnh = t;
        t = tcl; tcl = tnl; tnl = t;
    }

    // pool; h-fold; head
    pool_kernel<<<GG, HH>>>(tch, tcl, gstart, gmh, gml);
    gemm_tc<<<1, 256, SMEM_DYN>>>(gmh, gml, HH, HH, HH, nullptr, nullptr, 0,
                                  u23h, u23l, nullptr, nullptr,
                                  upd_b2 + 3*HH, nullptr, nullptr, nullptr, 0,
                                  ghh, ghl, nullptr, nullptr, nullptr, HH, HH, GG);
    gemm_tc<<<1, 256, SMEM_DYN>>>(ghh, ghl, HH, HH, HH, nullptr, nullptr, 0,
                                  hw1h, hw1l, nullptr, nullptr,
                                  head_b1, nullptr, nullptr, nullptr, 1,
                                  g2h, g2l, nullptr, nullptr, nullptr, HH, HH, GG);
    gemm_tc<<<1, 256, SMEM_DYN>>>(g2h, g2l, HH, HH, HH, nullptr, nullptr, 0,
                                  hw2h, hw2l, nullptr, nullptr,
                                  head_b2, nullptr, nullptr, nullptr, 0,
                                  nullptr, nullptr, (float*)d_out, nullptr, nullptr,
                                  OUTD, OUTD, GG);
}

// round 16
// speedup vs baseline: 1.0300x; 1.0300x over previous
#include <cuda_runtime.h>
#include <cuda_bf16.h>
#include <mma.h>
using namespace nvcuda;
typedef __nv_bfloat16 bf;

#define NN 50000
#define EE 800000
#define NFD 64
#define EFD 32
#define HH 96
#define OUTD 64
#define LL 4
#define GG 64
#define NH (NN*HH)
#define STAGE_B 33792          // Ah[5120]+Al[5120]+Wh[3328]+Wl[3328] bf16
#define SMEM_DYN (3*STAGE_B)   // triple buffer: 101376 B (2 blocks/SM ok)

// ------------------------------ scratch ------------------------------------
__device__ float d_f[3*NH + 4*LL*HH + NN];   // PT, PS, AGG(0-init), f*, bcomb, invdeg
__device__ bf d_pb[4*NH + 6*GG*HH + 2*(size_t)EE*EFD];  // tp planes, g*, ea planes
__device__ bf d_wpb[380928];                 // weight planes
__device__ int4 d_edat[EE];
__device__ int d_i[NN + (GG+1) + (NN+1) + NN + (GG+1)];

__device__ __forceinline__ void split1(float x, bf& h, bf& l) {
    h = __float2bfloat16_rn(x);
    l = __float2bfloat16_rn(x - __bfloat162float(h));
}
__device__ __forceinline__ unsigned pack2(bf a, bf b) {
    return ((unsigned)__bfloat16_as_ushort(b) << 16) | __bfloat16_as_ushort(a);
}
__device__ __forceinline__ void cpa16(bf* dst, const bf* src) {
    unsigned s = (unsigned)__cvta_generic_to_shared(dst);
    asm volatile("cp.async.cg.shared.global [%0], [%1], 16;" :: "r"(s), "l"(src));
}

// ------------------------------ setup --------------------------------------
__global__ void hist_both(const int* __restrict__ tgt, const int* __restrict__ batch,
                          int* __restrict__ deg, int* __restrict__ gcnt) {
    int i = blockIdx.x*blockDim.x + threadIdx.x;
    if (i < EE) atomicAdd(&deg[tgt[i]], 1);
    else if (i < EE + NN) atomicAdd(&gcnt[batch[i - EE]], 1);
}

__device__ void scan_seg(const int* __restrict__ in, int* __restrict__ out,
                         int* __restrict__ copy, int n, int* sums) {
    int lane = threadIdx.x & 31, wid = threadIdx.x >> 5, nwarp = blockDim.x >> 5;
    int offset = 0;
    for (int base = 0; base < n; base += blockDim.x) {
        int i = base + threadIdx.x;
        int v = (i < n) ? in[i] : 0, x = v;
        #pragma unroll
        for (int d = 1; d < 32; d <<= 1) { int y = __shfl_up_sync(~0u, x, d); if (lane >= d) x += y; }
        if (lane == 31) sums[wid] = x;
        __syncthreads();
        if (wid == 0) {
            int s = (lane < nwarp) ? sums[lane] : 0;
            #pragma unroll
            for (int d = 1; d < 32; d <<= 1) { int y = __shfl_up_sync(~0u, s, d); if (lane >= d) s += y; }
            sums[lane] = s;
        }
        __syncthreads();
        int warp_off = (wid > 0) ? sums[wid-1] : 0;
        if (i < n) { int val = offset + warp_off + x - v; out[i] = val; if (copy) copy[i] = val; }
        int total = sums[nwarp-1];
        __syncthreads();
        offset += total;
    }
    if (threadIdx.x == 0) out[n] = offset;
    __syncthreads();
}
__global__ void scan_both(const int* __restrict__ deg, int* __restrict__ rowptr,
                          int* __restrict__ cursor, const int* __restrict__ gcnt,
                          int* __restrict__ gstart) {
    __shared__ int sums[32];
    scan_seg(deg, rowptr, cursor, NN, sums);
    scan_seg(gcnt, gstart, nullptr, GG, sums);
}

__global__ void scatter_kernel(const int* __restrict__ src, const int* __restrict__ tgt,
                               int* __restrict__ cursor, int4* __restrict__ edat) {
    int e = blockIdx.x*blockDim.x + threadIdx.x;
    if (e < EE) {
        int t = tgt[e];
        int p = atomicAdd(&cursor[t], 1);
        edat[p] = make_int4(src[e], t, e, 0);
    }
}

#define E4 (EE*EFD/4)
__global__ void gather_split(const float* __restrict__ EA, const int4* __restrict__ edat,
                             const int* __restrict__ deg,
                             bf* __restrict__ eah, bf* __restrict__ eal,
                             float* __restrict__ invdeg) {
    int idx = blockIdx.x*blockDim.x + threadIdx.x;
    if (idx < E4) {
        int i = idx >> 3, f4 = idx & 7;
        int e = edat[i].z;
        float4 v = ((const float4*)(EA + (size_t)e*EFD))[f4];
        bf h0,l0,h1,l1,h2,l2,h3,l3;
        split1(v.x,h0,l0); split1(v.y,h1,l1); split1(v.z,h2,l2); split1(v.w,h3,l3);
        *(uint2*)(eah + (size_t)idx*4) = make_uint2(pack2(h0,h1), pack2(h2,h3));
        *(uint2*)(eal + (size_t)idx*4) = make_uint2(pack2(l0,l1), pack2(l2,l3));
    } else if (idx < E4 + NN) {
        int n = idx - E4;
        invdeg[n] = 1.f / (float)max(deg[n], 1);
    }
}

struct PackArgs { const float* src[8]; bf* dsth[8]; bf* dstl[8]; int n[8]; };
__global__ void pack_kernel(PackArgs a) {
    int s = blockIdx.y;
    int i = blockIdx.x*blockDim.x + threadIdx.x;
    if (i < a.n[s]) { bf h, l; split1(a.src[s][i], h, l); a.dsth[s][i] = h; a.dstl[s][i] = l; }
}

// Per-layer weight folds. blockIdx.x = l*4 + which.
__global__ void fold_kernel(
    const float* __restrict__ emb_w2, const float* __restrict__ emb_b2,
    const float* __restrict__ msg_w1, const float* __restrict__ msg_b1,
    const float* __restrict__ msg_w2, const float* __restrict__ msg_b2,
    const float* __restrict__ upd_w1, const float* __restrict__ upd_b1,
    const float* __restrict__ upd_w2, const float* __restrict__ upd_b2,
    bf* __restrict__ wfah, bf* __restrict__ wfal,
    bf* __restrict__ wfbh, bf* __restrict__ wfbl,
    bf* __restrict__ wu1h, bf* __restrict__ wu1l,
    float* __restrict__ fPT, float* __restrict__ fPS, float* __restrict__ fU,
    float* __restrict__ bcomb)
{
    int l = blockIdx.x >> 2, which = blockIdx.x & 3;
    const float* P;  const float* pb;
    const float* W;  const float* badd = nullptr;
    bf* Wh; bf* Wl;  float* bout;
    if (which == 3) {
        P = msg_w2 + (size_t)l*HH*HH;  pb = msg_b2 + l*HH;
        W = upd_w1 + (size_t)l*2*HH*HH + HH*HH;
        Wh = wu1h + (size_t)l*2*HH*HH + HH*HH; Wl = wu1l + (size_t)l*2*HH*HH + HH*HH;
        bout = bcomb + l*HH;
    } else {
        P  = (l == 0) ? emb_w2 : upd_w2 + (size_t)(l-1)*HH*HH;
        pb = (l == 0) ? emb_b2 : upd_b2 + (size_t)(l-1)*HH;
        if (which == 0) { W = msg_w1 + (size_t)l*(2*HH+EFD)*HH;
                          Wh = wfah + (size_t)l*HH*HH; Wl = wfal + (size_t)l*HH*HH;
                          bout = fPT + l*HH; badd = msg_b1 + l*HH; }
        else if (which == 1) { W = msg_w1 + (size_t)l*(2*HH+EFD)*HH + HH*HH;
                               Wh = wfbh + (size_t)l*HH*HH; Wl = wfbl + (size_t)l*HH*HH;
                               bout = fPS + l*HH; }
        else { W = upd_w1 + (size_t)l*2*HH*HH;
               Wh = wu1h + (size_t)l*2*HH*HH; Wl = wu1l + (size_t)l*2*HH*HH;
               bout = fU + l*HH; badd = upd_b1 + l*HH; }
    }
    for (int idx = threadIdx.x; idx < HH*HH; idx += blockDim.x) {
        int k = idx / HH, c = idx - k*HH;
        float s = 0.f;
        #pragma unroll 8
        for (int j = 0; j < HH; j++) s += P[k*HH + j] * W[j*HH + c];
        bf h, lo; split1(s, h, lo); Wh[idx] = h; Wl[idx] = lo;
    }
    for (int c = threadIdx.x; c < HH; c += blockDim.x) {
        float s = 0.f;
        for (int j = 0; j < HH; j++) s += pb[j] * W[j*HH + c];
        if (badd) s += badd[c];
        bout[c] = s;
    }
}

// --------------------------- MMA helper ------------------------------------
__device__ __forceinline__ void do_mma32(
    wmma::fragment<wmma::accumulator,16,16,16,float> (&acc)[2][3],
    const bf* Ah, const bf* Al, const bf* Wh, const bf* Wl, int wm, int wn) {
    #pragma unroll
    for (int ks = 0; ks < 32; ks += 16) {
        wmma::fragment<wmma::matrix_a,16,16,16,bf,wmma::row_major> ah[2], al2[2];
        wmma::fragment<wmma::matrix_b,16,16,16,bf,wmma::row_major> bh[3], bl[3];
        #pragma unroll
        for (int i = 0; i < 2; i++) {
            wmma::load_matrix_sync(ah[i],  &Ah[(wm + i*16)*40 + ks], 40);
            wmma::load_matrix_sync(al2[i], &Al[(wm + i*16)*40 + ks], 40);
        }
        #pragma unroll
        for (int j = 0; j < 3; j++) {
            wmma::load_matrix_sync(bh[j], &Wh[ks*104 + wn + j*16], 104);
            wmma::load_matrix_sync(bl[j], &Wl[ks*104 + wn + j*16], 104);
        }
        #pragma unroll
        for (int i = 0; i < 2; i++)
            #pragma unroll
            for (int j = 0; j < 3; j++) {
                wmma::mma_sync(acc[i][j], ah[i],  bh[j], acc[i][j]);
                wmma::mma_sync(acc[i][j], ah[i],  bl[j], acc[i][j]);
                wmma::mma_sync(acc[i][j], al2[i], bh[j], acc[i][j]);
            }
    }
}

// ---------- GEMM: cp.async triple-buffer, one sync/chunk, paired stores ------
__global__ void __launch_bounds__(256, 2) gemm_tc(
    const bf* __restrict__ A1h, const bf* __restrict__ A1l, int lda1, int K1, int K,
    const float* __restrict__ A2f, const float* __restrict__ Ainv, int lda2,
    const bf* __restrict__ Wah, const bf* __restrict__ Wal,
    const bf* __restrict__ Wbh, const bf* __restrict__ Wbl,
    const float* __restrict__ ba, const float* __restrict__ bb,
    const float* __restrict__ bx, const int* __restrict__ degmask, int relu,
    bf* __restrict__ oPh, bf* __restrict__ oPl,
    float* __restrict__ oF0, float* __restrict__ oF1, float* __restrict__ zbuf,
    int ldO, int Ncols, int M)
{
    extern __shared__ __align__(16) char sm[];
    float* Cs = (float*)sm;  // epilogue reuse (after final sync)

    const bf* Wgh = blockIdx.y ? Wbh : Wah;
    const bf* Wgl = blockIdx.y ? Wbl : Wal;
    const float* b = blockIdx.y ? bb : ba;
    float* oF = blockIdx.y ? oF1 : oF0;

    int tid = threadIdx.x, wid = tid >> 5;
    int bm0 = blockIdx.x * 128;
    int wm = (wid & 3) * 32, wn = (wid >> 2) * 48;
    int nch = K / 32;
    int segw = Ncols >> 3, wtot = 32 * segw;

    auto issue = [&](int ci) {
        int k0 = ci * 32;
        bf* Ah = (bf*)(sm + (ci % 3) * STAGE_B);
        bf* Al = Ah + 5120;
        bf* Wh = Al + 5120;
        bf* Wl = Wh + 3328;
        if (k0 < K1) {
            #pragma unroll
            for (int i = 0; i < 2; i++) {
                int p = tid + 256*i;                 // 512 segs of 16B
                int r = p >> 2, seg = p & 3;
                size_t go = (size_t)(bm0 + r)*lda1 + k0 + seg*8;
                cpa16(Ah + r*40 + seg*8, A1h + go);
                cpa16(Al + r*40 + seg*8, A1l + go);
            }
        } else {
            #pragma unroll
            for (int i = 0; i < 8; i++) {
                int p = tid + 256*i; int r = p >> 4, kc = (p & 15) << 1;
                int row = bm0 + r;
                float v0 = 0.f, v1 = 0.f;
                if (row < M) {
                    float d = Ainv ? Ainv[row] : 1.f;
                    const float* a = A2f + (size_t)row*lda2 + (k0 - K1) + kc;
                    v0 = a[0]*d; v1 = a[1]*d;
                }
                bf h0,l0,h1,l1; split1(v0,h0,l0); split1(v1,h1,l1);
                Ah[r*40+kc] = h0; Ah[r*40+kc+1] = h1;
                Al[r*40+kc] = l0; Al[r*40+kc+1] = l1;
            }
        }
        #pragma unroll
        for (int i = 0; i < 2; i++) {
            int p = tid + 256*i;
            if (p < wtot) {
                int kk = p / segw, seg = p - kk*segw;
                size_t go = (size_t)(k0 + kk)*Ncols + seg*8;
                cpa16(Wh + kk*104 + seg*8, Wgh + go);
                cpa16(Wl + kk*104 + seg*8, Wgl + go);
            }
        }
        asm volatile("cp.async.commit_group;");
    };

    wmma::fragment<wmma::accumulator,16,16,16,float> acc[2][3];
    #pragma unroll
    for (int i = 0; i < 2; i++)
        #pragma unroll
        for (int j = 0; j < 3; j++) wmma::fill_fragment(acc[i][j], 0.f);

    issue(0);
    if (nch > 1) issue(1);
    for (int c = 0; c < nch; c++) {
        if (c < nch - 1) asm volatile("cp.async.wait_group 1;");
        else             asm volatile("cp.async.wait_group 0;");
        __syncthreads();             // group c data visible to all warps;
                                     // also guarantees mma(c-1) complete
        if (c + 2 < nch) issue(c + 2);   // safe: buffer (c+2)%3 last used by mma(c-1)
        bf* Ah = (bf*)(sm + (c % 3) * STAGE_B);
        bf* Al = Ah + 5120;
        bf* Wh = Al + 5120;
        bf* Wl = Wh + 3328;
        do_mma32(acc, Ah, Al, Wh, Wl, wm, wn);
    }
    __syncthreads();                 // all MMAs done before Cs overwrites buffers

    #pragma unroll
    for (int i = 0; i < 2; i++)
        #pragma unroll
        for (int j = 0; j < 3; j++)
            wmma::store_matrix_sync(&Cs[(wm + i*16)*96 + wn + j*16], acc[i][j], 96,
                                    wmma::mem_row_major);
    __syncthreads();
    for (int p = tid; p < 6144; p += 256) {
        int r = p / 48, cc = (p - r*48) * 2;
        int row = bm0 + r;
        if (row >= M || cc >= Ncols) continue;
        float v0 = Cs[r*96 + cc], v1 = Cs[r*96 + cc + 1];
        if (b) { v0 += b[cc]; v1 += b[cc+1]; }
        if (bx && degmask[row] > 0) { v0 += bx[cc]; v1 += bx[cc+1]; }
        if (relu) { v0 = fmaxf(v0, 0.f); v1 = fmaxf(v1, 0.f); }
        size_t o = (size_t)row*ldO + cc;
        if (oPh) {
            bf h0,l0,h1,l1; split1(v0,h0,l0); split1(v1,h1,l1);
            *(unsigned*)(oPh + o) = pack2(h0, h1);
            *(unsigned*)(oPl + o) = pack2(l0, l1);
        }
        if (oF) *(float2*)(oF + o) = make_float2(v0, v1);
        if (zbuf && blockIdx.y == 0) *(float2*)(zbuf + o) = make_float2(0.f, 0.f);
    }
}

// ------------------------- fused edge kernel --------------------------------
__global__ void __launch_bounds__(256, 2) edge_fused(
    const bf* __restrict__ eah, const bf* __restrict__ eal,
    const bf* __restrict__ ech, const bf* __restrict__ ecl,
    const float* __restrict__ PT, const float* __restrict__ PS,
    const int4* __restrict__ edat, float* __restrict__ AGG)
{
    __shared__ __align__(16) char smraw[49152];
    bf* Ah = (bf*)smraw;
    bf* Al = Ah + 5120;
    bf* Wh = Al + 5120;
    bf* Wl = Wh + 3328;
    float* pes = (float*)smraw;     // [128][96]

    int tid = threadIdx.x, wid = tid >> 5, lane = tid & 31;
    int e0 = blockIdx.x * 128;
    int wm = (wid & 3) * 32, wn = (wid >> 2) * 48;

    #pragma unroll
    for (int i = 0; i < 2; i++) {
        int p = tid + 256*i;
        int r = p >> 2, seg = p & 3;
        size_t go = (size_t)(e0 + r)*EFD + seg*8;
        *(uint4*)&Ah[r*40 + seg*8] = *(const uint4*)(eah + go);
        *(uint4*)&Al[r*40 + seg*8] = *(const uint4*)(eal + go);
    }
    #pragma unroll
    for (int i = 0; i < 2; i++) {
        int p = tid + 256*i;
        if (p < 384) {
            int kk = p / 12, seg = p - kk*12;
            size_t go = (size_t)kk*96 + seg*8;
            *(uint4*)&Wh[kk*104 + seg*8] = *(const uint4*)(ech + go);
            *(uint4*)&Wl[kk*104 + seg*8] = *(const uint4*)(ecl + go);
        }
    }
    __syncthreads();

    wmma::fragment<wmma::accumulator,16,16,16,float> acc[2][3];
    #pragma unroll
    for (int i = 0; i < 2; i++)
        #pragma unroll
        for (int j = 0; j < 3; j++) wmma::fill_fragment(acc[i][j], 0.f);
    do_mma32(acc, Ah, Al, Wh, Wl, wm, wn);
    __syncthreads();
    #pragma unroll
    for (int i = 0; i < 2; i++)
        #pragma unroll
        for (int j = 0; j < 3; j++)
            wmma::store_matrix_sync(&pes[(wm + i*16)*96 + wn + j*16], acc[i][j], 96,
                                    wmma::mem_row_major);
    __syncthreads();

    int base = wid * 16;
    int4 ed = edat[e0 + base];
    float ps0 = PS[ed.x*96 + lane];
    float ps1 = PS[ed.x*96 + lane + 32];
    float ps2 = PS[ed.x*96 + lane + 64];
    int cur = -1;
    float a0 = 0.f, a1 = 0.f, a2 = 0.f, p0 = 0.f, p1 = 0.f, p2 = 0.f;
    #pragma unroll 4
    for (int j = 0; j < 16; j++) {
        int4 edn; float q0 = 0.f, q1 = 0.f, q2 = 0.f;
        if (j < 15) {
            edn = edat[e0 + base + j + 1];
            q0 = PS[edn.x*96 + lane];
            q1 = PS[edn.x*96 + lane + 32];
            q2 = PS[edn.x*96 + lane + 64];
        }
        int t = ed.y;
        if (t != cur) {
            if (cur >= 0) {
                atomicAdd(&AGG[cur*96 + lane],      a0);
                atomicAdd(&AGG[cur*96 + lane + 32], a1);
                atomicAdd(&AGG[cur*96 + lane + 64], a2);
            }
            cur = t; a0 = a1 = a2 = 0.f;
            p0 = PT[t*96 + lane]; p1 = PT[t*96 + lane + 32]; p2 = PT[t*96 + lane + 64];
        }
        const float* pr = &pes[(base + j)*96];
        a0 += fmaxf(p0 + ps0 + pr[lane],      0.f);
        a1 += fmaxf(p1 + ps1 + pr[lane + 32], 0.f);
        a2 += fmaxf(p2 + ps2 + pr[lane + 64], 0.f);
        ed = edn; ps0 = q0; ps1 = q1; ps2 = q2;
    }
    if (cur >= 0) {
        atomicAdd(&AGG[cur*96 + lane],      a0);
        atomicAdd(&AGG[cur*96 + lane + 32], a1);
        atomicAdd(&AGG[cur*96 + lane + 64], a2);
    }
}

__global__ void pool_kernel(const bf* __restrict__ hph, const bf* __restrict__ hpl,
                            const int* __restrict__ gstart,
                            bf* __restrict__ gmh, bf* __restrict__ gml) {
    int g = blockIdx.x, f = threadIdx.x;
    int beg = gstart[g], end = gstart[g+1];
    float s = 0.f;
    for (int r = beg; r < end; r++)
        s += __bfloat162float(hph[(size_t)r*96 + f]) + __bfloat162float(hpl[(size_t)r*96 + f]);
    s /= (float)max(end - beg, 1);
    bf h, l; split1(s, h, l);
    gmh[g*96 + f] = h; gml[g*96 + f] = l;
}

// ------------------------------- host --------------------------------------
extern "C" void kernel_launch(void* const* d_in, const int* in_sizes, int n_in,
                              void* d_out, int out_size) {
    const float* x          = (const float*)d_in[0];
    const float* edge_attr  = (const float*)d_in[1];
    const int*   edge_index = (const int*)d_in[2];
    const int*   batch      = (const int*)d_in[3];
    const float* emb_w1 = (const float*)d_in[4];  const float* emb_b1 = (const float*)d_in[5];
    const float* emb_w2 = (const float*)d_in[6];  const float* emb_b2 = (const float*)d_in[7];
    const float* msg_w1 = (const float*)d_in[8];  const float* msg_b1 = (const float*)d_in[9];
    const float* msg_w2 = (const float*)d_in[10]; const float* msg_b2 = (const float*)d_in[11];
    const float* upd_w1 = (const float*)d_in[12]; const float* upd_b1 = (const float*)d_in[13];
    const float* upd_w2 = (const float*)d_in[14]; const float* upd_b2 = (const float*)d_in[15];
    const float* head_w1 = (const float*)d_in[16]; const float* head_b1 = (const float*)d_in[17];
    const float* head_w2 = (const float*)d_in[18]; const float* head_b2 = (const float*)d_in[19];

    cudaFuncSetAttribute(gemm_tc, cudaFuncAttributeMaxDynamicSharedMemorySize, SMEM_DYN);

    float* f = nullptr; bf* pb = nullptr; bf* wb = nullptr;
    int* ib = nullptr; int4* edat = nullptr;
    cudaGetSymbolAddress((void**)&f, d_f);
    cudaGetSymbolAddress((void**)&pb, d_pb);
    cudaGetSymbolAddress((void**)&wb, d_wpb);
    cudaGetSymbolAddress((void**)&ib, d_i);
    cudaGetSymbolAddress((void**)&edat, d_edat);

    float* PT = f;  float* PS = f + NH;  float* AGG = f + 2*NH;
    float* fPT = f + 3*NH;          float* fPS = fPT + LL*HH;
    float* fU  = fPS + LL*HH;       float* bcomb = fU + LL*HH;
    float* invdeg = bcomb + LL*HH;

    bf* tpah = pb;            bf* tpal = tpah + NH;
    bf* tpbh = tpal + NH;     bf* tpbl = tpbh + NH;
    bf* gmh  = tpbl + NH;     bf* gml  = gmh + GG*HH;
    bf* ghh  = gml + GG*HH;   bf* ghl  = ghh + GG*HH;
    bf* g2h  = ghl + GG*HH;   bf* g2l  = g2h + GG*HH;
    bf* eah  = g2l + GG*HH;   bf* eal  = eah + (size_t)EE*EFD;

    bf* ewp1h = wb;             bf* ewp1l = ewp1h + 6144;
    bf* wfah = ewp1l + 6144;    bf* wfal = wfah + 36864;
    bf* wfbh = wfal + 36864;    bf* wfbl = wfbh + 36864;
    bf* wu1h = wfbl + 36864;    bf* wu1l = wu1h + 73728;
    bf* u23h = wu1l + 73728;    bf* u23l = u23h + 9216;
    bf* hw1h = u23l + 9216;     bf* hw1l = hw1h + 9216;
    bf* hw2h = hw1l + 9216;     bf* hw2l = hw2h + 6144;
    bf* ech  = hw2l + 6144;     bf* ecl  = ech + 12288;

    int* deg = ib;                 int* gcnt = deg + NN;
    int* rowptr = gcnt + GG + 1;   int* cursor = rowptr + NN + 1;
    int* gstart = cursor + NN;

    const int* src = edge_index;
    const int* tgt = edge_index + EE;

    int nb = (NN + 127)/128;

    // ---- weight chain first; dual PT/PS GEMM at ncu slot 4 ----
    {
        PackArgs a;
        a.src[0]=emb_w1;  a.dsth[0]=ewp1h; a.dstl[0]=ewp1l; a.n[0]=NFD*HH;
        for (int l = 0; l < LL; l++) {
            a.src[1+l] = msg_w1 + (size_t)l*(2*HH+EFD)*HH + 2*HH*HH;
            a.dsth[1+l] = ech + (size_t)l*EFD*HH;
            a.dstl[1+l] = ecl + (size_t)l*EFD*HH;
            a.n[1+l] = EFD*HH;
        }
        a.src[5]=upd_w2 + (size_t)3*HH*HH; a.dsth[5]=u23h; a.dstl[5]=u23l; a.n[5]=HH*HH;
        a.src[6]=head_w1; a.dsth[6]=hw1h; a.dstl[6]=hw1l; a.n[6]=HH*HH;
        a.src[7]=head_w2; a.dsth[7]=hw2h; a.dstl[7]=hw2l; a.n[7]=HH*OUTD;
        dim3 g((HH*HH + 255)/256, 8);
        pack_kernel<<<g, 256>>>(a);
    }
    fold_kernel<<<4*LL, 256>>>(emb_w2, emb_b2, msg_w1, msg_b1, msg_w2, msg_b2,
                               upd_w1, upd_b1, upd_w2, upd_b2,
                               wfah, wfal, wfbh, wfbl, wu1h, wu1l,
                               fPT, fPS, fU, bcomb);
    // embed stage-1: tpa = relu(x@ew1 + eb1)
    gemm_tc<<<nb, 256, SMEM_DYN>>>(nullptr, nullptr, 0, 0, NFD, x, nullptr, NFD,
                                   ewp1h, ewp1l, nullptr, nullptr,
                                   emb_b1, nullptr, nullptr, nullptr, 1,
                                   tpah, tpal, nullptr, nullptr, nullptr, HH, HH, NN);
    // layer-0 PT/PS (dual; y==0 zeroes AGG)   <- ncu slot 4
    gemm_tc<<<dim3(nb,2), 256, SMEM_DYN>>>(tpah, tpal, HH, HH, HH, nullptr, nullptr, 0,
                                           wfah, wfal, wfbh, wfbl,
                                           fPT, fPS, nullptr, nullptr, 0,
                                           nullptr, nullptr, PT, PS, AGG, HH, HH, NN);

    // ---- graph setup ----
    cudaMemsetAsync(deg, 0, (NN + GG + 1)*sizeof(int));
    hist_both<<<(EE + NN + 255)/256, 256>>>(tgt, batch, deg, gcnt);
    scan_both<<<1, 1024>>>(deg, rowptr, cursor, gcnt, gstart);
    scatter_kernel<<<(EE + 255)/256, 256>>>(src, tgt, cursor, edat);
    gather_split<<<(E4 + NN + 255)/256, 256>>>(edge_attr, edat, deg, eah, eal, invdeg);

    bf* tch = tpah; bf* tcl = tpal;
    bf* tnh = tpbh; bf* tnl = tpbl;
    for (int l = 0; l < LL; l++) {
        if (l > 0) {
            gemm_tc<<<dim3(nb,2), 256, SMEM_DYN>>>(tch, tcl, HH, HH, HH, nullptr, nullptr, 0,
                wfah + (size_t)l*HH*HH, wfal + (size_t)l*HH*HH,
                wfbh + (size_t)l*HH*HH, wfbl + (size_t)l*HH*HH,
                fPT + l*HH, fPS + l*HH, nullptr, nullptr, 0,
                nullptr, nullptr, PT, PS, AGG, HH, HH, NN);
        }
        edge_fused<<<EE/128, 256>>>(eah, eal, ech + (size_t)l*EFD*HH, ecl + (size_t)l*EFD*HH,
                                    PT, PS, edat, AGG);
        gemm_tc<<<nb, 256, SMEM_DYN>>>(tch, tcl, HH, HH, 2*HH, AGG, invdeg, HH,
            wu1h + (size_t)l*2*HH*HH, wu1l + (size_t)l*2*HH*HH, nullptr, nullptr,
            fU + l*HH, nullptr, bcomb + l*HH, deg, 1,
            tnh, tnl, nullptr, nullptr, nullptr, HH, HH, NN);
        bf* t;
        t = tch; tch = tnh; tnh = t;
        t = tcl; tcl = tnl; tnl = t;
    }

    // pool; h-fold; head
    pool_kernel<<<GG, HH>>>(tch, tcl, gstart, gmh, gml);
    gemm_tc<<<1, 256, SMEM_DYN>>>(gmh, gml, HH, HH, HH, nullptr, nullptr, 0,
                                  u23h, u23l, nullptr, nullptr,
                                  upd_b2 + 3*HH, nullptr, nullptr, nullptr, 0,
                                  ghh, ghl, nullptr, nullptr, nullptr, HH, HH, GG);
    gemm_tc<<<1, 256, SMEM_DYN>>>(ghh, ghl, HH, HH, HH, nullptr, nullptr, 0,
                                  hw1h, hw1l, nullptr, nullptr,
                                  head_b1, nullptr, nullptr, nullptr, 1,
                                  g2h, g2l, nullptr, nullptr, nullptr, HH, HH, GG);
    gemm_tc<<<1, 256, SMEM_DYN>>>(g2h, g2l, HH, HH, HH, nullptr, nullptr, 0,
                                  hw2h, hw2l, nullptr, nullptr,
                                  head_b2, nullptr, nullptr, nullptr, 0,
                                  nullptr, nullptr, (float*)d_out, nullptr, nullptr,
                                  OUTD, OUTD, GG);
}